// round 3
// baseline (speedup 1.0000x reference)
#include <cuda_runtime.h>
#include <cuda_fp16.h>
#include <math.h>

#define Cc   4
#define Nn   50000
#define NNZe 800000
#define CN   (Cc*Nn)          // 200000
#define TOT  (Cc*NNZe)        // 3200000
#define CAP  64
#define NROWB ((Nn+63)/64)    // 782

typedef unsigned long long u64;

// ---------------- scratch ----------------
__device__ int     g_is64;
__device__ int     g_deg[CN];
__device__ int     g_col[CN*CAP];        // 51.2 MB slot-CSR
__device__ __half2 g_Xh[Nn*32];          // 6.4 MB fp16 X
__device__ float   g_h[Nn*128];          // 25.6 MB
__device__ float   g_M[256*128];         // folded Ws@W0
__device__ float   g_sum[128];
__device__ float   g_sq[128];

// ---------------- packed f32x2 helpers ----------------
__device__ __forceinline__ void fma2(u64& acc, u64 a, u64 b) {
    asm("fma.rn.f32x2 %0, %1, %2, %0;" : "+l"(acc) : "l"(a), "l"(b));
}
__device__ __forceinline__ float2 up2(u64 v) {
    unsigned lo, hi;
    asm("mov.b64 {%0, %1}, %2;" : "=r"(lo), "=r"(hi) : "l"(v));
    return make_float2(__uint_as_float(lo), __uint_as_float(hi));
}

// ---------------- dummy (aligns ncu capture slot onto k_aggemm) ----------------
__global__ void k_dummy() {}

// ---------------- prep: zero deg/stats, probe dtype, fold M, convert X->fp16 ---
#define ZB 782
#define FB 128
#define XB ((Nn*32 + 255)/256)    // 6250
__global__ void k_prep(const void* __restrict__ A, const float* __restrict__ X,
                       const float* __restrict__ Ws, const float* __restrict__ W0) {
    int b = blockIdx.x;
    if (b < ZB) {
        int idx = b * 256 + threadIdx.x;
        if (idx < CN) g_deg[idx] = 0;
        if (idx < 128) { g_sum[idx] = 0.f; g_sq[idx] = 0.f; }
        if (idx == 0) {
            const int* a32 = (const int*)A;
            int is64 = 1;
            for (int i = 0; i < 64; i++) if (a32[2*i+1] != 0) { is64 = 0; break; }
            g_is64 = is64;
        }
    } else if (b < ZB + FB) {
        int idx = (b - ZB) * 256 + threadIdx.x;     // 32768 elems
        int r = idx >> 7, j = idx & 127;
        int c = r >> 6, f = r & 63;
        float acc = 0.f;
        #pragma unroll 16
        for (int g = 0; g < 64; g++)
            acc += Ws[(c*64 + f)*64 + g] * W0[(c*64 + g)*128 + j];
        g_M[idx] = acc;
    } else {
        int i = (b - ZB - FB) * 256 + threadIdx.x;  // half2 index
        if (i < Nn*32) {
            float2 v = ((const float2*)X)[i];
            g_Xh[i] = __floats2half2_rn(v.x, v.y);
        }
    }
}

// ---------------- build: slot-CSR in one pass ----------------
__global__ void k_build(const void* __restrict__ A) {
    int idx = blockIdx.x * blockDim.x + threadIdx.x;
    if (idx >= TOT) return;
    int is64 = g_is64;
    int c = idx / NNZe, e = idx - c*NNZe;
    long long base = (long long)c * 2 * NNZe;
    int dst, src;
    if (is64) {
        dst = ((const int*)A)[(base + e) * 2];
        src = ((const int*)A)[(base + NNZe + e) * 2];
    } else {
        dst = ((const int*)A)[base + e];
        src = ((const int*)A)[base + NNZe + e];
    }
    int w = c*Nn + dst;
    int slot = atomicAdd(&g_deg[w], 1);
    if (slot < CAP) g_col[w*CAP + slot] = src;
}

// ---------------- fused aggregation + GEMM1 (+ BN stats) ----------------
// block = 64 rows x 128 cols; 256 threads; colg=tid&31 (4 cols), rowg=tid>>5 (8 rows)
// smem: Msh [64][128] fp32 (32KB) + Ssh [64][128] duplicated-pair fp32 (32KB)
__global__ void __launch_bounds__(256, 3) k_aggemm(const float* __restrict__ b0) {
    extern __shared__ float smem[];
    float* Msh = smem;            // 8192 floats
    float* Ssh = smem + 8192;     // 8192 floats: row r, feat k dup at [r*128+2k, r*128+2k+1]
    int tid = threadIdx.x;
    int lane = tid & 31, wd = tid >> 5;
    int colg = tid & 31, rowg = tid >> 5;
    int hf = lane >> 4, fl = lane & 15;
    int row0 = blockIdx.x * 64;

    u64 acc[8][2];
    #pragma unroll
    for (int r = 0; r < 8; r++) { acc[r][0] = 0ull; acc[r][1] = 0ull; }

    for (int c = 0; c < 4; c++) {
        __syncthreads();
        // stage M tile (rows c*64 .. c*64+63) as float4
        {
            const float4* Mg = (const float4*)(g_M + c*64*128);
            float4* Ms4 = (float4*)Msh;
            #pragma unroll
            for (int i = 0; i < 8; i++) Ms4[tid + i*256] = Mg[tid + i*256];
        }
        // gather S tile: warp wd rows wd*8..wd*8+7; edge-parallel within warp
        for (int rr = 0; rr < 8; rr++) {
            int r = wd*8 + rr;
            int node = row0 + r;
            float4 a = make_float4(0.f, 0.f, 0.f, 0.f);
            if (node < Nn) {
                int w = c*Nn + node;
                int cnt = g_deg[w]; if (cnt > CAP) cnt = CAP;
                const int* colp = g_col + (long)w * CAP;
                for (int kk = 0; kk < cnt; kk += 32) {
                    int m = cnt - kk; if (m > 32) m = 32;
                    int idx = 0;
                    if (lane < m) idx = colp[kk + lane];
                    for (int k = 0; k < m; k += 2) {
                        int s = __shfl_sync(0xffffffffu, idx, k + hf);
                        if (k + hf < m) {
                            uint2 p = *(const uint2*)(g_Xh + s*32 + fl*2);
                            float2 f0 = __half22float2(*(__half2*)&p.x);
                            float2 f1 = __half22float2(*(__half2*)&p.y);
                            a.x += f0.x; a.y += f0.y; a.z += f1.x; a.w += f1.y;
                        }
                    }
                }
            }
            a.x += __shfl_xor_sync(0xffffffffu, a.x, 16);
            a.y += __shfl_xor_sync(0xffffffffu, a.y, 16);
            a.z += __shfl_xor_sync(0xffffffffu, a.z, 16);
            a.w += __shfl_xor_sync(0xffffffffu, a.w, 16);
            if (lane < 16) {
                float4* p = (float4*)&Ssh[r*128 + fl*8];
                p[0] = make_float4(a.x, a.x, a.y, a.y);
                p[1] = make_float4(a.z, a.z, a.w, a.w);
            }
        }
        __syncthreads();
        // FMA: per k: 1 LDS.128 (M cols) + 8 LDS.64 (S dup pairs) + 16 FFMA2
        const ulonglong2* M2 = (const ulonglong2*)Msh;
        #pragma unroll 4
        for (int k = 0; k < 64; k++) {
            ulonglong2 mm = M2[k*32 + colg];
            #pragma unroll
            for (int rr = 0; rr < 8; rr++) {
                u64 sv = *(const u64*)&Ssh[(rowg*8 + rr)*128 + 2*k];
                fma2(acc[rr][0], sv, mm.x);
                fma2(acc[rr][1], sv, mm.y);
            }
        }
    }

    // epilogue: bias, store h, BN partial sums
    float4 bb = ((const float4*)b0)[colg];
    float ps0=0,ps1=0,ps2=0,ps3=0, pq0=0,pq1=0,pq2=0,pq3=0;
    #pragma unroll
    for (int rr = 0; rr < 8; rr++) {
        int row = row0 + rowg*8 + rr;
        if (row < Nn) {
            float2 v01 = up2(acc[rr][0]);
            float2 v23 = up2(acc[rr][1]);
            float4 v;
            v.x = v01.x + bb.x; v.y = v01.y + bb.y;
            v.z = v23.x + bb.z; v.w = v23.y + bb.w;
            ((float4*)g_h)[row*32 + colg] = v;
            ps0 += v.x; ps1 += v.y; ps2 += v.z; ps3 += v.w;
            pq0 += v.x*v.x; pq1 += v.y*v.y; pq2 += v.z*v.z; pq3 += v.w*v.w;
        }
    }
    __syncthreads();
    float* bs = Ssh;
    float* bq = Ssh + 128;
    if (tid < 128) { bs[tid] = 0.f; bq[tid] = 0.f; }
    __syncthreads();
    atomicAdd(&bs[colg*4+0], ps0); atomicAdd(&bs[colg*4+1], ps1);
    atomicAdd(&bs[colg*4+2], ps2); atomicAdd(&bs[colg*4+3], ps3);
    atomicAdd(&bq[colg*4+0], pq0); atomicAdd(&bq[colg*4+1], pq1);
    atomicAdd(&bq[colg*4+2], pq2); atomicAdd(&bq[colg*4+3], pq3);
    __syncthreads();
    if (tid < 128) {
        atomicAdd(&g_sum[tid], bs[tid]);
        atomicAdd(&g_sq[tid],  bq[tid]);
    }
}

// ---------------- GEMM2: out = ELU(BN(h)) @ W1 + b1 ----------------
// block = 64 rows x 64 cols; 256 threads: cq=tid&15 (4 cols), rg=tid>>4 (4 rows)
// dyn smem: hs [64][128] dup-pair (64KB) + Wsh [128][64] (32KB)
__global__ void __launch_bounds__(256, 2) k_gemm2(const float* __restrict__ W1,
                                                  const float* __restrict__ b1,
                                                  const float* __restrict__ gamma,
                                                  const float* __restrict__ beta,
                                                  float* __restrict__ out) {
    extern __shared__ float smem[];
    float* hs  = smem;             // 16384 floats
    float* Wsh = smem + 16384;     // 8192 floats
    __shared__ float sc[128], sf[128];
    int tid = threadIdx.x;
    int cq = tid & 15, rg = tid >> 4;
    int row0 = blockIdx.x * 64;

    if (tid < 128) {
        float m = g_sum[tid] * (1.f / Nn);
        float var = g_sq[tid] * (1.f / Nn) - m*m;
        float r = rsqrtf(var + 1e-5f);
        float s = r * gamma[tid];
        sc[tid] = s;
        sf[tid] = beta[tid] - m*s;
    }
    {   // stage W1
        const float4* Wg = (const float4*)W1;
        float4* Ws4 = (float4*)Wsh;
        #pragma unroll
        for (int i = 0; i < 8; i++) Ws4[tid + i*256] = Wg[tid + i*256];
    }
    __syncthreads();
    for (int idx = tid; idx < 64*128; idx += 256) {
        int r = idx >> 7, k = idx & 127;
        int row = row0 + r;
        float v = 0.f;
        if (row < Nn) {
            v = g_h[row*128 + k] * sc[k] + sf[k];
            v = v > 0.f ? v : expm1f(v);
        }
        ((float2*)hs)[r*128 + k] = make_float2(v, v);
    }
    __syncthreads();

    u64 acc[4][2];
    #pragma unroll
    for (int i = 0; i < 4; i++) { acc[i][0] = 0ull; acc[i][1] = 0ull; }
    const ulonglong2* W2 = (const ulonglong2*)Wsh;
    #pragma unroll 4
    for (int k = 0; k < 128; k++) {
        ulonglong2 ww = W2[k*16 + cq];
        #pragma unroll
        for (int i = 0; i < 4; i++) {
            u64 sv = *(const u64*)&hs[(rg*4 + i)*256 + 2*k];
            fma2(acc[i][0], sv, ww.x);
            fma2(acc[i][1], sv, ww.y);
        }
    }
    float4 bb = ((const float4*)b1)[cq];
    #pragma unroll
    for (int i = 0; i < 4; i++) {
        int row = row0 + rg*4 + i;
        if (row < Nn) {
            float2 v01 = up2(acc[i][0]);
            float2 v23 = up2(acc[i][1]);
            float4 v;
            v.x = v01.x + bb.x; v.y = v01.y + bb.y;
            v.z = v23.x + bb.z; v.w = v23.y + bb.w;
            ((float4*)out)[row*16 + cq] = v;
        }
    }
}

// ---------------- launch ----------------
extern "C" void kernel_launch(void* const* d_in, const int* in_sizes, int n_in,
                              void* d_out, int out_size) {
    const void*  A     = d_in[0];
    const float* X     = (const float*)d_in[1];
    const float* Ws    = (const float*)d_in[2];
    const float* W0    = (const float*)d_in[3];
    const float* b0    = (const float*)d_in[4];
    const float* gamma = (const float*)d_in[5];
    const float* beta  = (const float*)d_in[6];
    const float* W1    = (const float*)d_in[7];
    const float* b1    = (const float*)d_in[8];
    float* out = (float*)d_out;

    cudaFuncSetAttribute(k_aggemm, cudaFuncAttributeMaxDynamicSharedMemorySize, 65536);
    cudaFuncSetAttribute(k_gemm2,  cudaFuncAttributeMaxDynamicSharedMemorySize, 98304);

    k_dummy<<<1, 32>>>();
    k_prep<<<ZB + FB + XB, 256>>>(A, X, Ws, W0);
    k_build<<<(TOT + 255)/256, 256>>>(A);
    k_aggemm<<<NROWB, 256, 65536>>>(b0);
    k_gemm2<<<NROWB, 256, 98304>>>(W1, b1, gamma, beta, out);
}

// round 4
// speedup vs baseline: 1.2540x; 1.2540x over previous
#include <cuda_runtime.h>
#include <cuda_fp16.h>
#include <math.h>

#define Cc   4
#define Nn   50000
#define NNZe 800000
#define CN   (Cc*Nn)          // 200000
#define TOT  (Cc*NNZe)        // 3200000
#define CAP  64
#define NROWB ((Nn+63)/64)    // 782

typedef unsigned long long u64;

// ---------------- scratch ----------------
__device__ int     g_is64;
__device__ int     g_deg[CN];
__device__ int     g_col[CN*CAP];        // 51.2 MB slot-CSR
__device__ __half2 g_Xh[Nn*32];          // 6.4 MB fp16 X
__device__ float   g_S[Nn*256];          // 51.2 MB aggregated features [N, C*64]
__device__ float   g_h[Nn*128];          // 25.6 MB
__device__ float   g_M[256*128];         // folded Ws@W0
__device__ float   g_sum[128];
__device__ float   g_sq[128];

// ---------------- packed f32x2 helpers ----------------
__device__ __forceinline__ void fma2(u64& acc, u64 a, u64 b) {
    asm("fma.rn.f32x2 %0, %1, %2, %0;" : "+l"(acc) : "l"(a), "l"(b));
}
__device__ __forceinline__ float2 up2(u64 v) {
    unsigned lo, hi;
    asm("mov.b64 {%0, %1}, %2;" : "=r"(lo), "=r"(hi) : "l"(v));
    return make_float2(__uint_as_float(lo), __uint_as_float(hi));
}

// ---------------- prep: zero deg/stats, probe dtype, fold M, convert X->fp16 ---
#define ZB 782
#define FB 128
#define XB ((Nn*32 + 255)/256)    // 6250
__global__ void k_prep(const void* __restrict__ A, const float* __restrict__ X,
                       const float* __restrict__ Ws, const float* __restrict__ W0) {
    int b = blockIdx.x;
    if (b < ZB) {
        int idx = b * 256 + threadIdx.x;
        if (idx < CN) g_deg[idx] = 0;
        if (idx < 128) { g_sum[idx] = 0.f; g_sq[idx] = 0.f; }
        if (idx == 0) {
            const int* a32 = (const int*)A;
            int is64 = 1;
            for (int i = 0; i < 64; i++) if (a32[2*i+1] != 0) { is64 = 0; break; }
            g_is64 = is64;
        }
    } else if (b < ZB + FB) {
        int idx = (b - ZB) * 256 + threadIdx.x;     // 32768 elems
        int r = idx >> 7, j = idx & 127;
        int c = r >> 6, f = r & 63;
        float acc = 0.f;
        #pragma unroll 16
        for (int g = 0; g < 64; g++)
            acc += Ws[(c*64 + f)*64 + g] * W0[(c*64 + g)*128 + j];
        g_M[idx] = acc;
    } else {
        int i = (b - ZB - FB) * 256 + threadIdx.x;  // half2 index
        if (i < Nn*32) {
            float2 v = ((const float2*)X)[i];
            g_Xh[i] = __floats2half2_rn(v.x, v.y);
        }
    }
}

// ---------------- build: slot-CSR in one pass ----------------
__global__ void k_build(const void* __restrict__ A) {
    int idx = blockIdx.x * blockDim.x + threadIdx.x;
    if (idx >= TOT) return;
    int is64 = g_is64;
    int c = idx / NNZe, e = idx - c*NNZe;
    long long base = (long long)c * 2 * NNZe;
    int dst, src;
    if (is64) {
        dst = ((const int*)A)[(base + e) * 2];
        src = ((const int*)A)[(base + NNZe + e) * 2];
    } else {
        dst = ((const int*)A)[base + e];
        src = ((const int*)A)[base + NNZe + e];
    }
    int w = c*Nn + dst;
    int slot = atomicAdd(&g_deg[w], 1);
    if (slot < CAP) g_col[w*CAP + slot] = src;
}

// ---------------- aggregation: warp per (cat,node), lane owns half2 feature ----
// 200K warps; per edge one independent LDG.32 per lane; uniform index loads.
__global__ void __launch_bounds__(256) k_agg() {
    int w = (blockIdx.x * blockDim.x + threadIdx.x) >> 5;
    int lane = threadIdx.x & 31;
    if (w >= CN) return;
    int c = w / Nn, i = w - c*Nn;
    int cnt = g_deg[w]; if (cnt > CAP) cnt = CAP;
    const int* colp = g_col + (long)w * CAP;
    const __half2* Xr = g_Xh + lane;

    float2 acc = make_float2(0.f, 0.f);
    int k = 0;
    for (; k + 8 <= cnt; k += 8) {
        int s0 = colp[k],   s1 = colp[k+1], s2 = colp[k+2], s3 = colp[k+3];
        int s4 = colp[k+4], s5 = colp[k+5], s6 = colp[k+6], s7 = colp[k+7];
        float2 f0 = __half22float2(Xr[s0*32]);
        float2 f1 = __half22float2(Xr[s1*32]);
        float2 f2 = __half22float2(Xr[s2*32]);
        float2 f3 = __half22float2(Xr[s3*32]);
        float2 f4 = __half22float2(Xr[s4*32]);
        float2 f5 = __half22float2(Xr[s5*32]);
        float2 f6 = __half22float2(Xr[s6*32]);
        float2 f7 = __half22float2(Xr[s7*32]);
        acc.x += ((f0.x + f1.x) + (f2.x + f3.x)) + ((f4.x + f5.x) + (f6.x + f7.x));
        acc.y += ((f0.y + f1.y) + (f2.y + f3.y)) + ((f4.y + f5.y) + (f6.y + f7.y));
    }
    for (; k < cnt; k++) {
        float2 f = __half22float2(Xr[colp[k]*32]);
        acc.x += f.x; acc.y += f.y;
    }
    ((float2*)g_S)[i*128 + c*32 + lane] = acc;
}

// ---------------- GEMM1: h = S @ M + b0, fused BN stats ----------------
// block = 64 rows x 128 cols; 256 threads; colg=tid&31 (4 cols), rowg=tid>>5 (8 rows)
// dyn smem: Msh [64][128] fp32 (32KB) + Ssh [64][64] dup-pair (32KB)
__global__ void __launch_bounds__(256, 3) k_gemm1(const float* __restrict__ b0) {
    extern __shared__ float smem[];
    float* Msh = smem;            // 8192 floats
    float* Ssh = smem + 8192;     // 8192 floats: row r, feat k dup at [r*128+2k]
    int tid = threadIdx.x;
    int colg = tid & 31, rowg = tid >> 5;
    int row0 = blockIdx.x * 64;

    u64 acc[8][2];
    #pragma unroll
    for (int r = 0; r < 8; r++) { acc[r][0] = 0ull; acc[r][1] = 0ull; }

    for (int c = 0; c < 4; c++) {
        __syncthreads();
        // stage M tile
        {
            const float4* Mg = (const float4*)(g_M + c*64*128);
            float4* Ms4 = (float4*)Msh;
            #pragma unroll
            for (int i = 0; i < 8; i++) Ms4[tid + i*256] = Mg[tid + i*256];
        }
        // stage S tile with duplicated pairs: 64 rows x 32 float2 each
        #pragma unroll
        for (int i = 0; i < 8; i++) {
            int idx = tid + i*256;        // 0..2047
            int r = idx >> 5, j2 = idx & 31;
            int row = row0 + r;
            float2 v = (row < Nn) ? ((const float2*)g_S)[row*128 + c*32 + j2]
                                  : make_float2(0.f, 0.f);
            *(float4*)&Ssh[r*128 + 4*j2] = make_float4(v.x, v.x, v.y, v.y);
        }
        __syncthreads();
        const ulonglong2* M2 = (const ulonglong2*)Msh;
        #pragma unroll 4
        for (int k = 0; k < 64; k++) {
            ulonglong2 mm = M2[k*32 + colg];
            #pragma unroll
            for (int rr = 0; rr < 8; rr++) {
                u64 sv = *(const u64*)&Ssh[(rowg*8 + rr)*128 + 2*k];
                fma2(acc[rr][0], sv, mm.x);
                fma2(acc[rr][1], sv, mm.y);
            }
        }
    }

    // epilogue: bias, store h, BN partial sums
    float4 bb = ((const float4*)b0)[colg];
    float ps0=0,ps1=0,ps2=0,ps3=0, pq0=0,pq1=0,pq2=0,pq3=0;
    #pragma unroll
    for (int rr = 0; rr < 8; rr++) {
        int row = row0 + rowg*8 + rr;
        if (row < Nn) {
            float2 v01 = up2(acc[rr][0]);
            float2 v23 = up2(acc[rr][1]);
            float4 v;
            v.x = v01.x + bb.x; v.y = v01.y + bb.y;
            v.z = v23.x + bb.z; v.w = v23.y + bb.w;
            ((float4*)g_h)[row*32 + colg] = v;
            ps0 += v.x; ps1 += v.y; ps2 += v.z; ps3 += v.w;
            pq0 += v.x*v.x; pq1 += v.y*v.y; pq2 += v.z*v.z; pq3 += v.w*v.w;
        }
    }
    __syncthreads();
    float* bs = Ssh;
    float* bq = Ssh + 128;
    if (tid < 128) { bs[tid] = 0.f; bq[tid] = 0.f; }
    __syncthreads();
    atomicAdd(&bs[colg*4+0], ps0); atomicAdd(&bs[colg*4+1], ps1);
    atomicAdd(&bs[colg*4+2], ps2); atomicAdd(&bs[colg*4+3], ps3);
    atomicAdd(&bq[colg*4+0], pq0); atomicAdd(&bq[colg*4+1], pq1);
    atomicAdd(&bq[colg*4+2], pq2); atomicAdd(&bq[colg*4+3], pq3);
    __syncthreads();
    if (tid < 128) {
        atomicAdd(&g_sum[tid], bs[tid]);
        atomicAdd(&g_sq[tid],  bq[tid]);
    }
}

// ---------------- GEMM2: out = ELU(BN(h)) @ W1 + b1 ----------------
// block = 64 rows x 64 cols; 256 threads: cq=tid&15 (4 cols), rg=tid>>4 (4 rows)
// dyn smem: hs [64][128] dup-pair (64KB) + Wsh [128][64] (32KB)
__global__ void __launch_bounds__(256, 2) k_gemm2(const float* __restrict__ W1,
                                                  const float* __restrict__ b1,
                                                  const float* __restrict__ gamma,
                                                  const float* __restrict__ beta,
                                                  float* __restrict__ out) {
    extern __shared__ float smem[];
    float* hs  = smem;             // 16384 floats
    float* Wsh = smem + 16384;     // 8192 floats
    __shared__ float sc[128], sf[128];
    int tid = threadIdx.x;
    int cq = tid & 15, rg = tid >> 4;
    int row0 = blockIdx.x * 64;

    if (tid < 128) {
        float m = g_sum[tid] * (1.f / Nn);
        float var = g_sq[tid] * (1.f / Nn) - m*m;
        float r = rsqrtf(var + 1e-5f);
        float s = r * gamma[tid];
        sc[tid] = s;
        sf[tid] = beta[tid] - m*s;
    }
    {   // stage W1
        const float4* Wg = (const float4*)W1;
        float4* Ws4 = (float4*)Wsh;
        #pragma unroll
        for (int i = 0; i < 8; i++) Ws4[tid + i*256] = Wg[tid + i*256];
    }
    __syncthreads();
    for (int idx = tid; idx < 64*128; idx += 256) {
        int r = idx >> 7, k = idx & 127;
        int row = row0 + r;
        float v = 0.f;
        if (row < Nn) {
            v = g_h[row*128 + k] * sc[k] + sf[k];
            v = v > 0.f ? v : expm1f(v);
        }
        ((float2*)hs)[r*128 + k] = make_float2(v, v);
    }
    __syncthreads();

    u64 acc[4][2];
    #pragma unroll
    for (int i = 0; i < 4; i++) { acc[i][0] = 0ull; acc[i][1] = 0ull; }
    const ulonglong2* W2 = (const ulonglong2*)Wsh;
    #pragma unroll 4
    for (int k = 0; k < 128; k++) {
        ulonglong2 ww = W2[k*16 + cq];
        #pragma unroll
        for (int i = 0; i < 4; i++) {
            u64 sv = *(const u64*)&hs[(rg*4 + i)*256 + 2*k];
            fma2(acc[i][0], sv, ww.x);
            fma2(acc[i][1], sv, ww.y);
        }
    }
    float4 bb = ((const float4*)b1)[cq];
    #pragma unroll
    for (int i = 0; i < 4; i++) {
        int row = row0 + rg*4 + i;
        if (row < Nn) {
            float2 v01 = up2(acc[i][0]);
            float2 v23 = up2(acc[i][1]);
            float4 v;
            v.x = v01.x + bb.x; v.y = v01.y + bb.y;
            v.z = v23.x + bb.z; v.w = v23.y + bb.w;
            ((float4*)out)[row*16 + cq] = v;
        }
    }
}

// ---------------- launch ----------------
extern "C" void kernel_launch(void* const* d_in, const int* in_sizes, int n_in,
                              void* d_out, int out_size) {
    const void*  A     = d_in[0];
    const float* X     = (const float*)d_in[1];
    const float* Ws    = (const float*)d_in[2];
    const float* W0    = (const float*)d_in[3];
    const float* b0    = (const float*)d_in[4];
    const float* gamma = (const float*)d_in[5];
    const float* beta  = (const float*)d_in[6];
    const float* W1    = (const float*)d_in[7];
    const float* b1    = (const float*)d_in[8];
    float* out = (float*)d_out;

    cudaFuncSetAttribute(k_gemm1, cudaFuncAttributeMaxDynamicSharedMemorySize, 65536);
    cudaFuncSetAttribute(k_gemm2, cudaFuncAttributeMaxDynamicSharedMemorySize, 98304);

    k_prep<<<ZB + FB + XB, 256>>>(A, X, Ws, W0);
    k_build<<<(TOT + 255)/256, 256>>>(A);
    k_agg<<<(CN*32 + 255)/256, 256>>>();            // 4th-slot candidate below
    k_gemm1<<<NROWB, 256, 65536>>>(b0);
    k_gemm2<<<NROWB, 256, 98304>>>(W1, b1, gamma, beta, out);
}

// round 5
// speedup vs baseline: 1.3016x; 1.0379x over previous
#include <cuda_runtime.h>
#include <cuda_fp16.h>
#include <math.h>

#define Cc   4
#define Nn   50000
#define NNZe 800000
#define CN   (Cc*Nn)          // 200000
#define TOT  (Cc*NNZe)        // 3200000
#define CAP  64
#define NROWB ((Nn+63)/64)    // 782

typedef unsigned long long u64;

// ---------------- scratch ----------------
__device__ int     g_is64;
__device__ int     g_deg[CN];
__device__ int     g_col[CN*CAP];        // 51.2 MB slot-CSR
__device__ __half2 g_Xh[Nn*32];          // 6.4 MB fp16 X
__device__ __half2 g_Sh[Nn*128];         // 25.6 MB aggregated S, fp16 [N, 256]
__device__ float   g_h[Nn*128];          // 25.6 MB
__device__ float   g_M[256*128];         // folded Ws@W0
__device__ float   g_sum[128];
__device__ float   g_sq[128];

// ---------------- packed f32x2 helpers ----------------
__device__ __forceinline__ void fma2(u64& acc, u64 a, u64 b) {
    asm("fma.rn.f32x2 %0, %1, %2, %0;" : "+l"(acc) : "l"(a), "l"(b));
}
__device__ __forceinline__ float2 up2(u64 v) {
    unsigned lo, hi;
    asm("mov.b64 {%0, %1}, %2;" : "=r"(lo), "=r"(hi) : "l"(v));
    return make_float2(__uint_as_float(lo), __uint_as_float(hi));
}

// ---------------- prep: zero deg/stats, probe dtype, fold M, convert X->fp16 ---
#define ZB 782
#define FB 128
#define XB ((Nn*32 + 255)/256)    // 6250
__global__ void k_prep(const void* __restrict__ A, const float* __restrict__ X,
                       const float* __restrict__ Ws, const float* __restrict__ W0) {
    int b = blockIdx.x;
    if (b < ZB) {
        int idx = b * 256 + threadIdx.x;
        if (idx < CN) g_deg[idx] = 0;
        if (idx < 128) { g_sum[idx] = 0.f; g_sq[idx] = 0.f; }
        if (idx == 0) {
            const int* a32 = (const int*)A;
            int is64 = 1;
            for (int i = 0; i < 64; i++) if (a32[2*i+1] != 0) { is64 = 0; break; }
            g_is64 = is64;
        }
    } else if (b < ZB + FB) {
        int idx = (b - ZB) * 256 + threadIdx.x;     // 32768 elems
        int r = idx >> 7, j = idx & 127;
        int c = r >> 6, f = r & 63;
        float acc = 0.f;
        #pragma unroll 16
        for (int g = 0; g < 64; g++)
            acc += Ws[(c*64 + f)*64 + g] * W0[(c*64 + g)*128 + j];
        g_M[idx] = acc;
    } else {
        int i = (b - ZB - FB) * 256 + threadIdx.x;  // half2 index
        if (i < Nn*32) {
            float2 v = ((const float2*)X)[i];
            g_Xh[i] = __floats2half2_rn(v.x, v.y);
        }
    }
}

// ---------------- build: slot-CSR in one pass ----------------
__global__ void k_build(const void* __restrict__ A) {
    int idx = blockIdx.x * blockDim.x + threadIdx.x;
    if (idx >= TOT) return;
    int is64 = g_is64;
    int c = idx / NNZe, e = idx - c*NNZe;
    long long base = (long long)c * 2 * NNZe;
    int dst, src;
    if (is64) {
        dst = ((const int*)A)[(base + e) * 2];
        src = ((const int*)A)[(base + NNZe + e) * 2];
    } else {
        dst = ((const int*)A)[base + e];
        src = ((const int*)A)[base + NNZe + e];
    }
    int w = c*Nn + dst;
    int slot = atomicAdd(&g_deg[w], 1);
    if (slot < CAP) g_col[w*CAP + slot] = src;
}

// ---------------- aggregation: warp per (cat,node), lane owns half2 feature ----
__global__ void __launch_bounds__(256) k_agg() {
    int w = (blockIdx.x * blockDim.x + threadIdx.x) >> 5;
    int lane = threadIdx.x & 31;
    if (w >= CN) return;
    int c = w / Nn, i = w - c*Nn;
    int cnt = g_deg[w]; if (cnt > CAP) cnt = CAP;
    const int* colp = g_col + (long)w * CAP;
    const __half2* Xr = g_Xh + lane;

    float2 acc = make_float2(0.f, 0.f);
    int k = 0;
    for (; k + 8 <= cnt; k += 8) {
        int s0 = colp[k],   s1 = colp[k+1], s2 = colp[k+2], s3 = colp[k+3];
        int s4 = colp[k+4], s5 = colp[k+5], s6 = colp[k+6], s7 = colp[k+7];
        float2 f0 = __half22float2(Xr[s0*32]);
        float2 f1 = __half22float2(Xr[s1*32]);
        float2 f2 = __half22float2(Xr[s2*32]);
        float2 f3 = __half22float2(Xr[s3*32]);
        float2 f4 = __half22float2(Xr[s4*32]);
        float2 f5 = __half22float2(Xr[s5*32]);
        float2 f6 = __half22float2(Xr[s6*32]);
        float2 f7 = __half22float2(Xr[s7*32]);
        acc.x += ((f0.x + f1.x) + (f2.x + f3.x)) + ((f4.x + f5.x) + (f6.x + f7.x));
        acc.y += ((f0.y + f1.y) + (f2.y + f3.y)) + ((f4.y + f5.y) + (f6.y + f7.y));
    }
    for (; k < cnt; k++) {
        float2 f = __half22float2(Xr[colp[k]*32]);
        acc.x += f.x; acc.y += f.y;
    }
    g_Sh[i*128 + c*32 + lane] = __floats2half2_rn(acc.x, acc.y);
}

// ---------------- GEMM1: h = S @ M + b0, fused BN stats ----------------
// block = 64 rows x 128 cols; 256 threads; colg=tid&31 (4 cols), rowg=tid>>5 (8 rows)
// dyn smem: Msh [64][128] fp32 (32KB) + Ssh [64 rows][64 k dup-pair] (32KB)
// paired-k inner loop: one broadcast LDS.128 of S serves 2 k-steps.
__global__ void __launch_bounds__(256, 3) k_gemm1(const float* __restrict__ b0) {
    extern __shared__ float smem[];
    float* Msh = smem;            // 8192 floats
    float* Ssh = smem + 8192;     // 8192 floats: row r, k dup at [r*128+2k]
    int tid = threadIdx.x;
    int colg = tid & 31, rowg = tid >> 5;
    int row0 = blockIdx.x * 64;

    u64 acc[8][2];
    #pragma unroll
    for (int r = 0; r < 8; r++) { acc[r][0] = 0ull; acc[r][1] = 0ull; }

    for (int c = 0; c < 4; c++) {
        __syncthreads();
        // stage M tile
        {
            const float4* Mg = (const float4*)(g_M + c*64*128);
            float4* Ms4 = (float4*)Msh;
            #pragma unroll
            for (int i = 0; i < 8; i++) Ms4[tid + i*256] = Mg[tid + i*256];
        }
        // stage S tile (fp16 -> fp32 dup-pairs): 64 rows x 32 half2 each
        #pragma unroll
        for (int i = 0; i < 8; i++) {
            int idx = tid + i*256;        // 0..2047
            int r = idx >> 5, j2 = idx & 31;
            int row = row0 + r;
            float2 v = make_float2(0.f, 0.f);
            if (row < Nn) v = __half22float2(g_Sh[row*128 + c*32 + j2]);
            *(float4*)&Ssh[r*128 + 4*j2] = make_float4(v.x, v.x, v.y, v.y);
        }
        __syncthreads();
        const ulonglong2* M2 = (const ulonglong2*)Msh;
        #pragma unroll 4
        for (int k = 0; k < 64; k += 2) {
            ulonglong2 mm0 = M2[k*32 + colg];
            ulonglong2 mm1 = M2[(k+1)*32 + colg];
            #pragma unroll
            for (int rr = 0; rr < 8; rr++) {
                ulonglong2 ss = *(const ulonglong2*)&Ssh[(rowg*8 + rr)*128 + 2*k];
                fma2(acc[rr][0], ss.x, mm0.x);
                fma2(acc[rr][1], ss.x, mm0.y);
                fma2(acc[rr][0], ss.y, mm1.x);
                fma2(acc[rr][1], ss.y, mm1.y);
            }
        }
    }

    // epilogue: bias, store h, BN partial sums
    float4 bb = ((const float4*)b0)[colg];
    float ps0=0,ps1=0,ps2=0,ps3=0, pq0=0,pq1=0,pq2=0,pq3=0;
    #pragma unroll
    for (int rr = 0; rr < 8; rr++) {
        int row = row0 + rowg*8 + rr;
        if (row < Nn) {
            float2 v01 = up2(acc[rr][0]);
            float2 v23 = up2(acc[rr][1]);
            float4 v;
            v.x = v01.x + bb.x; v.y = v01.y + bb.y;
            v.z = v23.x + bb.z; v.w = v23.y + bb.w;
            ((float4*)g_h)[row*32 + colg] = v;
            ps0 += v.x; ps1 += v.y; ps2 += v.z; ps3 += v.w;
            pq0 += v.x*v.x; pq1 += v.y*v.y; pq2 += v.z*v.z; pq3 += v.w*v.w;
        }
    }
    __syncthreads();
    float* bs = Ssh;
    float* bq = Ssh + 128;
    if (tid < 128) { bs[tid] = 0.f; bq[tid] = 0.f; }
    __syncthreads();
    atomicAdd(&bs[colg*4+0], ps0); atomicAdd(&bs[colg*4+1], ps1);
    atomicAdd(&bs[colg*4+2], ps2); atomicAdd(&bs[colg*4+3], ps3);
    atomicAdd(&bq[colg*4+0], pq0); atomicAdd(&bq[colg*4+1], pq1);
    atomicAdd(&bq[colg*4+2], pq2); atomicAdd(&bq[colg*4+3], pq3);
    __syncthreads();
    if (tid < 128) {
        atomicAdd(&g_sum[tid], bs[tid]);
        atomicAdd(&g_sq[tid],  bq[tid]);
    }
}

// ---------------- GEMM2: out = ELU(BN(h)) @ W1 + b1 ----------------
// block = 64 rows x 64 cols; 256 threads: cq=tid&15 (4 cols), rg=tid>>4 (4 rows)
// dyn smem: hs [64][128] dup-pair (64KB) + Wsh [128][64] (32KB); paired-k loop.
__global__ void __launch_bounds__(256, 2) k_gemm2(const float* __restrict__ W1,
                                                  const float* __restrict__ b1,
                                                  const float* __restrict__ gamma,
                                                  const float* __restrict__ beta,
                                                  float* __restrict__ out) {
    extern __shared__ float smem[];
    float* hs  = smem;             // 16384 floats
    float* Wsh = smem + 16384;     // 8192 floats
    __shared__ float sc[128], sf[128];
    int tid = threadIdx.x;
    int cq = tid & 15, rg = tid >> 4;
    int row0 = blockIdx.x * 64;

    if (tid < 128) {
        float m = g_sum[tid] * (1.f / Nn);
        float var = g_sq[tid] * (1.f / Nn) - m*m;
        float r = rsqrtf(var + 1e-5f);
        float s = r * gamma[tid];
        sc[tid] = s;
        sf[tid] = beta[tid] - m*s;
    }
    {   // stage W1
        const float4* Wg = (const float4*)W1;
        float4* Ws4 = (float4*)Wsh;
        #pragma unroll
        for (int i = 0; i < 8; i++) Ws4[tid + i*256] = Wg[tid + i*256];
    }
    __syncthreads();
    for (int idx = tid; idx < 64*128; idx += 256) {
        int r = idx >> 7, k = idx & 127;
        int row = row0 + r;
        float v = 0.f;
        if (row < Nn) {
            v = g_h[row*128 + k] * sc[k] + sf[k];
            v = v > 0.f ? v : expm1f(v);
        }
        ((float2*)hs)[r*128 + k] = make_float2(v, v);
    }
    __syncthreads();

    u64 acc[4][2];
    #pragma unroll
    for (int i = 0; i < 4; i++) { acc[i][0] = 0ull; acc[i][1] = 0ull; }
    const ulonglong2* W2 = (const ulonglong2*)Wsh;
    #pragma unroll 4
    for (int k = 0; k < 128; k += 2) {
        ulonglong2 ww0 = W2[k*16 + cq];
        ulonglong2 ww1 = W2[(k+1)*16 + cq];
        #pragma unroll
        for (int i = 0; i < 4; i++) {
            ulonglong2 ss = *(const ulonglong2*)&hs[(rg*4 + i)*256 + 2*k];
            fma2(acc[i][0], ss.x, ww0.x);
            fma2(acc[i][1], ss.x, ww0.y);
            fma2(acc[i][0], ss.y, ww1.x);
            fma2(acc[i][1], ss.y, ww1.y);
        }
    }
    float4 bb = ((const float4*)b1)[cq];
    #pragma unroll
    for (int i = 0; i < 4; i++) {
        int row = row0 + rg*4 + i;
        if (row < Nn) {
            float2 v01 = up2(acc[i][0]);
            float2 v23 = up2(acc[i][1]);
            float4 v;
            v.x = v01.x + bb.x; v.y = v01.y + bb.y;
            v.z = v23.x + bb.z; v.w = v23.y + bb.w;
            ((float4*)out)[row*16 + cq] = v;
        }
    }
}

// ---------------- launch ----------------
extern "C" void kernel_launch(void* const* d_in, const int* in_sizes, int n_in,
                              void* d_out, int out_size) {
    const void*  A     = d_in[0];
    const float* X     = (const float*)d_in[1];
    const float* Ws    = (const float*)d_in[2];
    const float* W0    = (const float*)d_in[3];
    const float* b0    = (const float*)d_in[4];
    const float* gamma = (const float*)d_in[5];
    const float* beta  = (const float*)d_in[6];
    const float* W1    = (const float*)d_in[7];
    const float* b1    = (const float*)d_in[8];
    float* out = (float*)d_out;

    cudaFuncSetAttribute(k_gemm1, cudaFuncAttributeMaxDynamicSharedMemorySize, 65536);
    cudaFuncSetAttribute(k_gemm2, cudaFuncAttributeMaxDynamicSharedMemorySize, 98304);

    k_prep<<<ZB + FB + XB, 256>>>(A, X, Ws, W0);
    k_build<<<(TOT + 255)/256, 256>>>(A);
    k_agg<<<(CN*32 + 255)/256, 256>>>();
    k_gemm1<<<NROWB, 256, 65536>>>(b0);        // 4th launch -> ncu slot
    k_gemm2<<<NROWB, 256, 98304>>>(W1, b1, gamma, beta, out);
}

// round 7
// speedup vs baseline: 1.7934x; 1.3778x over previous
#include <cuda_runtime.h>
#include <cuda_fp16.h>
#include <mma.h>
#include <math.h>
#include <cstdint>

using namespace nvcuda;

#define Cc   4
#define Nn   50000
#define NNZe 800000
#define CN   (Cc*Nn)          // 200000
#define TOT  (Cc*NNZe)        // 3200000
#define CAP  64
#define NROWB ((Nn+63)/64)    // 782
#define NMB   ((Nn+127)/128)  // 391 gemm1 blocks
#define NPAD  (NMB*128)       // 50048 padded rows for g_h
#define LDX   136             // padded smem leading dim (halves / floats)

typedef unsigned long long u64;

// ---------------- scratch ----------------
__device__ int     g_is64;
__device__ int     g_deg[CN];
__device__ int     g_col[CN*CAP];        // 51.2 MB slot-CSR
__device__ __half2 g_Xh[Nn*32];          // 6.4 MB fp16 X
__device__ __half2 g_Sh[Nn*128];         // 25.6 MB aggregated S, fp16 [N,256] K-major
__device__ __half  g_Mt[128*256];        // 64 KB folded (Ws@W0)^T fp16: [j][k]
__device__ float   g_h[NPAD*128];        // 25.6 MB (padded)
__device__ float   g_sum[128];
__device__ float   g_sq[128];

// ---------------- packed f32x2 helpers (gemm2) ----------------
__device__ __forceinline__ void fma2(u64& acc, u64 a, u64 b) {
    asm("fma.rn.f32x2 %0, %1, %2, %0;" : "+l"(acc) : "l"(a), "l"(b));
}
__device__ __forceinline__ float2 up2(u64 v) {
    unsigned lo, hi;
    asm("mov.b64 {%0, %1}, %2;" : "=r"(lo), "=r"(hi) : "l"(v));
    return make_float2(__uint_as_float(lo), __uint_as_float(hi));
}

// ---------------- dummy (ncu 4th-slot alignment -> k_agg) ----------------
__global__ void k_dummy() {}

// ---------------- prep ----------------
#define ZB 782
#define FB 128
#define XB ((Nn*32 + 255)/256)    // 6250
__global__ void k_prep(const void* __restrict__ A, const float* __restrict__ X,
                       const float* __restrict__ Ws, const float* __restrict__ W0) {
    int b = blockIdx.x;
    if (b < ZB) {
        int idx = b * 256 + threadIdx.x;
        if (idx < CN) g_deg[idx] = 0;
        if (idx < 128) { g_sum[idx] = 0.f; g_sq[idx] = 0.f; }
        if (idx == 0) {
            const int* a32 = (const int*)A;
            int is64 = 1;
            for (int i = 0; i < 64; i++) if (a32[2*i+1] != 0) { is64 = 0; break; }
            g_is64 = is64;
        }
    } else if (b < ZB + FB) {
        int idx = (b - ZB) * 256 + threadIdx.x;     // 32768 elems
        int r = idx >> 7, j = idx & 127;            // r = k index (c*64+f)
        int c = r >> 6, f = r & 63;
        float acc = 0.f;
        #pragma unroll 16
        for (int g = 0; g < 64; g++)
            acc += Ws[(c*64 + f)*64 + g] * W0[(c*64 + g)*128 + j];
        g_Mt[j*256 + r] = __float2half(acc);        // [j][k], K contiguous
    } else {
        int i = (b - ZB - FB) * 256 + threadIdx.x;  // half2 index
        if (i < Nn*32) {
            float2 v = ((const float2*)X)[i];
            g_Xh[i] = __floats2half2_rn(v.x, v.y);
        }
    }
}

// ---------------- build: slot-CSR in one pass ----------------
__global__ void k_build(const void* __restrict__ A) {
    int idx = blockIdx.x * blockDim.x + threadIdx.x;
    if (idx >= TOT) return;
    int is64 = g_is64;
    int c = idx / NNZe, e = idx - c*NNZe;
    long long base = (long long)c * 2 * NNZe;
    int dst, src;
    if (is64) {
        dst = ((const int*)A)[(base + e) * 2];
        src = ((const int*)A)[(base + NNZe + e) * 2];
    } else {
        dst = ((const int*)A)[base + e];
        src = ((const int*)A)[base + NNZe + e];
    }
    int w = c*Nn + dst;
    int slot = atomicAdd(&g_deg[w], 1);
    if (slot < CAP) g_col[w*CAP + slot] = src;
}

// ---------------- aggregation: warp per (cat,node), lane owns half2 feature ----
__global__ void __launch_bounds__(256) k_agg() {
    int w = (blockIdx.x * blockDim.x + threadIdx.x) >> 5;
    int lane = threadIdx.x & 31;
    if (w >= CN) return;
    int c = w / Nn, i = w - c*Nn;
    int cnt = g_deg[w]; if (cnt > CAP) cnt = CAP;
    const int* colp = g_col + (long)w * CAP;
    const __half2* Xr = g_Xh + lane;

    float2 acc = make_float2(0.f, 0.f);
    int k = 0;
    for (; k + 8 <= cnt; k += 8) {
        int s0 = colp[k],   s1 = colp[k+1], s2 = colp[k+2], s3 = colp[k+3];
        int s4 = colp[k+4], s5 = colp[k+5], s6 = colp[k+6], s7 = colp[k+7];
        float2 f0 = __half22float2(Xr[s0*32]);
        float2 f1 = __half22float2(Xr[s1*32]);
        float2 f2 = __half22float2(Xr[s2*32]);
        float2 f3 = __half22float2(Xr[s3*32]);
        float2 f4 = __half22float2(Xr[s4*32]);
        float2 f5 = __half22float2(Xr[s5*32]);
        float2 f6 = __half22float2(Xr[s6*32]);
        float2 f7 = __half22float2(Xr[s7*32]);
        acc.x += ((f0.x + f1.x) + (f2.x + f3.x)) + ((f4.x + f5.x) + (f6.x + f7.x));
        acc.y += ((f0.y + f1.y) + (f2.y + f3.y)) + ((f4.y + f5.y) + (f6.y + f7.y));
    }
    for (; k < cnt; k++) {
        float2 f = __half22float2(Xr[colp[k]*32]);
        acc.x += f.x; acc.y += f.y;
    }
    g_Sh[i*128 + c*32 + lane] = __floats2half2_rn(acc.x, acc.y);
}

// ---------------- GEMM1 via wmma/HMMA: h = S @ M + b0 ----------------
// CTA 256 thr = 8 warps (4m x 2n). Block tile 128x128, K=256 in 2 chunks of 128.
// dyn smem: Ssh [128][LDX] f16 + Msh [128][LDX] f16 (Mt rows n, cols k-chunk).
__global__ void __launch_bounds__(256, 2) k_gemm1wm(const float* __restrict__ b0) {
    extern __shared__ __half sh[];
    __half* Ssh = sh;                 // [row m][k] ld=LDX
    __half* Msh = sh + 128*LDX;       // [n][k]     ld=LDX (col-major B)
    __shared__ float biasTile[16*LDX];

    int tid = threadIdx.x;
    int wid = tid >> 5;
    int warp_m = wid >> 1;            // 0..3 -> 32 rows each
    int warp_n = wid & 1;             // 0..1 -> 64 cols each
    int row0 = blockIdx.x * 128;

    // bias tile: 16 identical rows of b0
    for (int idx = tid; idx < 16*128; idx += 256) {
        int r = idx >> 7, c = idx & 127;
        biasTile[r*LDX + c] = b0[c];
    }
    __syncthreads();

    wmma::fragment<wmma::accumulator, 16,16,16, float> acc[2][4];
    #pragma unroll
    for (int i = 0; i < 2; i++)
        #pragma unroll
        for (int j = 0; j < 4; j++)
            wmma::load_matrix_sync(acc[i][j],
                biasTile + (warp_n*64 + j*16), LDX, wmma::mem_row_major);

    #pragma unroll
    for (int kc = 0; kc < 2; kc++) {
        __syncthreads();
        // stage S chunk: 128 rows x 128 halves (16 uint4 per row)
        for (int idx = tid; idx < 2048; idx += 256) {
            int r = idx >> 4, ch = idx & 15;
            uint4 v = make_uint4(0,0,0,0);
            int node = row0 + r;
            if (node < Nn) v = ((const uint4*)g_Sh)[node*32 + kc*16 + ch];
            *(uint4*)&Ssh[r*LDX + ch*8] = v;
        }
        // stage Mt chunk: 128 n-rows x 128 k
        for (int idx = tid; idx < 2048; idx += 256) {
            int n = idx >> 4, ch = idx & 15;
            uint4 v = ((const uint4*)g_Mt)[n*32 + kc*16 + ch];
            *(uint4*)&Msh[n*LDX + ch*8] = v;
        }
        __syncthreads();

        #pragma unroll
        for (int ks = 0; ks < 8; ks++) {
            wmma::fragment<wmma::matrix_a, 16,16,16, __half, wmma::row_major> af[2];
            wmma::fragment<wmma::matrix_b, 16,16,16, __half, wmma::col_major> bf[4];
            #pragma unroll
            for (int i = 0; i < 2; i++)
                wmma::load_matrix_sync(af[i],
                    Ssh + (warp_m*32 + i*16)*LDX + ks*16, LDX);
            #pragma unroll
            for (int j = 0; j < 4; j++)
                wmma::load_matrix_sync(bf[j],
                    Msh + (warp_n*64 + j*16)*LDX + ks*16, LDX);
            #pragma unroll
            for (int i = 0; i < 2; i++)
                #pragma unroll
                for (int j = 0; j < 4; j++)
                    wmma::mma_sync(acc[i][j], af[i], bf[j], acc[i][j]);
        }
    }

    // store to (padded) g_h
    #pragma unroll
    for (int i = 0; i < 2; i++)
        #pragma unroll
        for (int j = 0; j < 4; j++) {
            int r = row0 + warp_m*32 + i*16;
            int c = warp_n*64 + j*16;
            wmma::store_matrix_sync(g_h + (long)r*128 + c, acc[i][j], 128,
                                    wmma::mem_row_major);
        }
}

// ---------------- BN stats over g_h ----------------
__global__ void __launch_bounds__(256) k_stats() {
    __shared__ float ss[256], qq[256];
    int tid = threadIdx.x;
    int col = tid & 127, half = tid >> 7;
    int row0 = blockIdx.x * 64;
    float s = 0.f, q = 0.f;
    for (int r = half; r < 64; r += 2) {
        int row = row0 + r;
        if (row < Nn) {
            float v = g_h[row*128 + col];
            s += v; q += v*v;
        }
    }
    ss[tid] = s; qq[tid] = q;
    __syncthreads();
    if (tid < 128) {
        atomicAdd(&g_sum[tid], ss[tid] + ss[tid+128]);
        atomicAdd(&g_sq[tid],  qq[tid] + qq[tid+128]);
    }
}

// ---------------- GEMM2: out = ELU(BN(h)) @ W1 + b1 ----------------
__global__ void __launch_bounds__(256, 2) k_gemm2(const float* __restrict__ W1,
                                                  const float* __restrict__ b1,
                                                  const float* __restrict__ gamma,
                                                  const float* __restrict__ beta,
                                                  float* __restrict__ out) {
    extern __shared__ float smem[];
    float* hs  = smem;             // 16384 floats (dup-pair)
    float* Wsh = smem + 16384;     // 8192 floats
    __shared__ float sc[128], sf[128];
    int tid = threadIdx.x;
    int cq = tid & 15, rg = tid >> 4;
    int row0 = blockIdx.x * 64;

    if (tid < 128) {
        float m = g_sum[tid] * (1.f / Nn);
        float var = g_sq[tid] * (1.f / Nn) - m*m;
        float r = rsqrtf(var + 1e-5f);
        float s = r * gamma[tid];
        sc[tid] = s;
        sf[tid] = beta[tid] - m*s;
    }
    {
        const float4* Wg = (const float4*)W1;
        float4* Ws4 = (float4*)Wsh;
        #pragma unroll
        for (int i = 0; i < 8; i++) Ws4[tid + i*256] = Wg[tid + i*256];
    }
    __syncthreads();
    for (int idx = tid; idx < 64*128; idx += 256) {
        int r = idx >> 7, k = idx & 127;
        int row = row0 + r;
        float v = 0.f;
        if (row < Nn) {
            v = g_h[row*128 + k] * sc[k] + sf[k];
            v = v > 0.f ? v : expm1f(v);
        }
        ((float2*)hs)[r*128 + k] = make_float2(v, v);
    }
    __syncthreads();

    u64 acc[4][2];
    #pragma unroll
    for (int i = 0; i < 4; i++) { acc[i][0] = 0ull; acc[i][1] = 0ull; }
    const ulonglong2* W2 = (const ulonglong2*)Wsh;
    #pragma unroll 4
    for (int k = 0; k < 128; k += 2) {
        ulonglong2 ww0 = W2[k*16 + cq];
        ulonglong2 ww1 = W2[(k+1)*16 + cq];
        #pragma unroll
        for (int i = 0; i < 4; i++) {
            ulonglong2 ss = *(const ulonglong2*)&hs[(rg*4 + i)*256 + 2*k];
            fma2(acc[i][0], ss.x, ww0.x);
            fma2(acc[i][1], ss.x, ww0.y);
            fma2(acc[i][0], ss.y, ww1.x);
            fma2(acc[i][1], ss.y, ww1.y);
        }
    }
    float4 bb = ((const float4*)b1)[cq];
    #pragma unroll
    for (int i = 0; i < 4; i++) {
        int row = row0 + rg*4 + i;
        if (row < Nn) {
            float2 v01 = up2(acc[i][0]);
            float2 v23 = up2(acc[i][1]);
            float4 v;
            v.x = v01.x + bb.x; v.y = v01.y + bb.y;
            v.z = v23.x + bb.z; v.w = v23.y + bb.w;
            ((float4*)out)[row*16 + cq] = v;
        }
    }
}

// ---------------- launch ----------------
extern "C" void kernel_launch(void* const* d_in, const int* in_sizes, int n_in,
                              void* d_out, int out_size) {
    const void*  A     = d_in[0];
    const float* X     = (const float*)d_in[1];
    const float* Ws    = (const float*)d_in[2];
    const float* W0    = (const float*)d_in[3];
    const float* b0    = (const float*)d_in[4];
    const float* gamma = (const float*)d_in[5];
    const float* beta  = (const float*)d_in[6];
    const float* W1    = (const float*)d_in[7];
    const float* b1    = (const float*)d_in[8];
    float* out = (float*)d_out;

    const int g1_smem = 2 * 128 * LDX * (int)sizeof(__half);   // 69632
    cudaFuncSetAttribute(k_gemm1wm, cudaFuncAttributeMaxDynamicSharedMemorySize, g1_smem);
    cudaFuncSetAttribute(k_gemm2,   cudaFuncAttributeMaxDynamicSharedMemorySize, 98304);

    k_dummy<<<1, 32>>>();
    k_prep<<<ZB + FB + XB, 256>>>(A, X, Ws, W0);
    k_build<<<(TOT + 255)/256, 256>>>(A);
    k_agg<<<(CN*32 + 255)/256, 256>>>();        // 4th launch -> ncu slot
    k_gemm1wm<<<NMB, 256, g1_smem>>>(b0);
    k_stats<<<NROWB, 256>>>();
    k_gemm2<<<NROWB, 256, 98304>>>(W1, b1, gamma, beta, out);
}

// round 8
// speedup vs baseline: 1.8790x; 1.0478x over previous
#include <cuda_runtime.h>
#include <cuda_fp16.h>
#include <mma.h>
#include <math.h>
#include <cstdint>

using namespace nvcuda;

#define Cc   4
#define Nn   50000
#define NNZe 800000
#define CN   (Cc*Nn)          // 200000
#define TOT  (Cc*NNZe)        // 3200000
#define CAP  64
#define NROWB ((Nn+63)/64)    // 782
#define NMB   ((Nn+127)/128)  // 391
#define NPAD  (NMB*128)       // 50048
#define LDX   136             // padded smem leading dim (halves)

typedef unsigned long long u64;

// ---------------- scratch ----------------
__device__ int     g_is64;
__device__ int     g_deg[CN];
__device__ int     g_col[CN*CAP];        // 51.2 MB slot-CSR
__device__ __half2 g_Xh[Nn*32];          // 6.4 MB fp16 X
__device__ __half2 g_Sh[Nn*128];         // 25.6 MB aggregated S fp16 [N,256]
__device__ __half  g_Mt[128*256];        // folded (Ws@W0)^T fp16: [j][k]
__device__ __half  g_W1t[64*128];        // W1^T fp16: [n][k]
__device__ float   g_h[NPAD*128];        // 25.6 MB (padded)
__device__ float   g_sum[128];
__device__ float   g_sq[128];

// ---------------- dummy (ncu slot alignment -> k_agg) ----------------
__global__ void k_dummy() {}

// ---------------- prep ----------------
#define ZB  782
#define FB  128
#define W1B 32
#define XB  ((Nn*32 + 255)/256)    // 6250
__global__ void k_prep(const void* __restrict__ A, const float* __restrict__ X,
                       const float* __restrict__ Ws, const float* __restrict__ W0,
                       const float* __restrict__ W1) {
    int b = blockIdx.x;
    if (b < ZB) {
        int idx = b * 256 + threadIdx.x;
        if (idx < CN) g_deg[idx] = 0;
        if (idx < 128) { g_sum[idx] = 0.f; g_sq[idx] = 0.f; }
        if (idx == 0) {
            const int* a32 = (const int*)A;
            int is64 = 1;
            for (int i = 0; i < 64; i++) if (a32[2*i+1] != 0) { is64 = 0; break; }
            g_is64 = is64;
        }
    } else if (b < ZB + FB) {
        int idx = (b - ZB) * 256 + threadIdx.x;     // 32768 elems
        int r = idx >> 7, j = idx & 127;            // r = k (c*64+f)
        int c = r >> 6, f = r & 63;
        float acc = 0.f;
        #pragma unroll 16
        for (int g = 0; g < 64; g++)
            acc += Ws[(c*64 + f)*64 + g] * W0[(c*64 + g)*128 + j];
        g_Mt[j*256 + r] = __float2half(acc);        // [j][k]
    } else if (b < ZB + FB + W1B) {
        int idx = (b - ZB - FB) * 256 + threadIdx.x;   // 8192 elems: n*128+k
        int n = idx >> 7, k = idx & 127;
        g_W1t[idx] = __float2half(W1[k*64 + n]);
    } else {
        int i = (b - ZB - FB - W1B) * 256 + threadIdx.x;
        if (i < Nn*32) {
            float2 v = ((const float2*)X)[i];
            g_Xh[i] = __floats2half2_rn(v.x, v.y);
        }
    }
}

// ---------------- build: slot-CSR in one pass ----------------
__global__ void k_build(const void* __restrict__ A) {
    int idx = blockIdx.x * blockDim.x + threadIdx.x;
    if (idx >= TOT) return;
    int is64 = g_is64;
    int c = idx / NNZe, e = idx - c*NNZe;
    long long base = (long long)c * 2 * NNZe;
    int dst, src;
    if (is64) {
        dst = ((const int*)A)[(base + e) * 2];
        src = ((const int*)A)[(base + NNZe + e) * 2];
    } else {
        dst = ((const int*)A)[base + e];
        src = ((const int*)A)[base + NNZe + e];
    }
    int w = c*Nn + dst;
    int slot = atomicAdd(&g_deg[w], 1);
    if (slot < CAP) g_col[w*CAP + slot] = src;
}

// ---------------- aggregation: warp per (cat,node) ----------------
// int4 index loads; fp16 pair pre-reduction (1 HADD2 / 2 edges), fp32 flush.
__global__ void __launch_bounds__(256) k_agg() {
    int w = (blockIdx.x * blockDim.x + threadIdx.x) >> 5;
    int lane = threadIdx.x & 31;
    if (w >= CN) return;
    int c = w / Nn, i = w - c*Nn;
    int cnt = g_deg[w]; if (cnt > CAP) cnt = CAP;
    const int* colp = g_col + (long)w * CAP;
    const __half2* Xr = g_Xh + lane;

    float2 acc = make_float2(0.f, 0.f);
    int k = 0;
    for (; k + 8 <= cnt; k += 8) {
        int4 i0 = *(const int4*)(colp + k);
        int4 i1 = *(const int4*)(colp + k + 4);
        __half2 p0 = __hadd2(Xr[i0.x*32], Xr[i0.y*32]);
        __half2 p1 = __hadd2(Xr[i0.z*32], Xr[i0.w*32]);
        __half2 p2 = __hadd2(Xr[i1.x*32], Xr[i1.y*32]);
        __half2 p3 = __hadd2(Xr[i1.z*32], Xr[i1.w*32]);
        float2 f0 = __half22float2(p0);
        float2 f1 = __half22float2(p1);
        float2 f2 = __half22float2(p2);
        float2 f3 = __half22float2(p3);
        acc.x += (f0.x + f1.x) + (f2.x + f3.x);
        acc.y += (f0.y + f1.y) + (f2.y + f3.y);
    }
    if (k + 4 <= cnt) {
        int4 i0 = *(const int4*)(colp + k);
        __half2 p0 = __hadd2(Xr[i0.x*32], Xr[i0.y*32]);
        __half2 p1 = __hadd2(Xr[i0.z*32], Xr[i0.w*32]);
        float2 f0 = __half22float2(p0);
        float2 f1 = __half22float2(p1);
        acc.x += f0.x + f1.x;
        acc.y += f0.y + f1.y;
        k += 4;
    }
    for (; k < cnt; k++) {
        float2 f = __half22float2(Xr[colp[k]*32]);
        acc.x += f.x; acc.y += f.y;
    }
    g_Sh[i*128 + c*32 + lane] = __floats2half2_rn(acc.x, acc.y);
}

// ---------------- GEMM1 via wmma: h = S @ M + b0 ----------------
__global__ void __launch_bounds__(256, 2) k_gemm1wm(const float* __restrict__ b0) {
    extern __shared__ __half sh[];
    __half* Ssh = sh;                 // [m][k] ld=LDX
    __half* Msh = sh + 128*LDX;       // [n][k] ld=LDX
    __shared__ float biasTile[16*LDX];

    int tid = threadIdx.x;
    int wid = tid >> 5;
    int warp_m = wid >> 1;
    int warp_n = wid & 1;
    int row0 = blockIdx.x * 128;

    for (int idx = tid; idx < 16*128; idx += 256) {
        int r = idx >> 7, cc = idx & 127;
        biasTile[r*LDX + cc] = b0[cc];
    }
    __syncthreads();

    wmma::fragment<wmma::accumulator, 16,16,16, float> acc[2][4];
    #pragma unroll
    for (int i = 0; i < 2; i++)
        #pragma unroll
        for (int j = 0; j < 4; j++)
            wmma::load_matrix_sync(acc[i][j],
                biasTile + (warp_n*64 + j*16), LDX, wmma::mem_row_major);

    #pragma unroll
    for (int kc = 0; kc < 2; kc++) {
        __syncthreads();
        for (int idx = tid; idx < 2048; idx += 256) {
            int r = idx >> 4, ch = idx & 15;
            uint4 v = make_uint4(0,0,0,0);
            int node = row0 + r;
            if (node < Nn) v = ((const uint4*)g_Sh)[node*32 + kc*16 + ch];
            *(uint4*)&Ssh[r*LDX + ch*8] = v;
        }
        for (int idx = tid; idx < 2048; idx += 256) {
            int n = idx >> 4, ch = idx & 15;
            uint4 v = ((const uint4*)g_Mt)[n*32 + kc*16 + ch];
            *(uint4*)&Msh[n*LDX + ch*8] = v;
        }
        __syncthreads();

        #pragma unroll
        for (int ks = 0; ks < 8; ks++) {
            wmma::fragment<wmma::matrix_a, 16,16,16, __half, wmma::row_major> af[2];
            wmma::fragment<wmma::matrix_b, 16,16,16, __half, wmma::col_major> bf[4];
            #pragma unroll
            for (int i = 0; i < 2; i++)
                wmma::load_matrix_sync(af[i], Ssh + (warp_m*32 + i*16)*LDX + ks*16, LDX);
            #pragma unroll
            for (int j = 0; j < 4; j++)
                wmma::load_matrix_sync(bf[j], Msh + (warp_n*64 + j*16)*LDX + ks*16, LDX);
            #pragma unroll
            for (int i = 0; i < 2; i++)
                #pragma unroll
                for (int j = 0; j < 4; j++)
                    wmma::mma_sync(acc[i][j], af[i], bf[j], acc[i][j]);
        }
    }

    #pragma unroll
    for (int i = 0; i < 2; i++)
        #pragma unroll
        for (int j = 0; j < 4; j++) {
            int r = row0 + warp_m*32 + i*16;
            int cc = warp_n*64 + j*16;
            wmma::store_matrix_sync(g_h + (long)r*128 + cc, acc[i][j], 128,
                                    wmma::mem_row_major);
        }
}

// ---------------- BN stats over g_h ----------------
__global__ void __launch_bounds__(256) k_stats() {
    __shared__ float ss[256], qq[256];
    int tid = threadIdx.x;
    int col = tid & 127, half = tid >> 7;
    int row0 = blockIdx.x * 64;
    float s = 0.f, q = 0.f;
    for (int r = half; r < 64; r += 2) {
        int row = row0 + r;
        if (row < Nn) {
            float v = g_h[row*128 + col];
            s += v; q += v*v;
        }
    }
    ss[tid] = s; qq[tid] = q;
    __syncthreads();
    if (tid < 128) {
        atomicAdd(&g_sum[tid], ss[tid] + ss[tid+128]);
        atomicAdd(&g_sq[tid],  qq[tid] + qq[tid+128]);
    }
}

// ---------------- GEMM2 via wmma: out = ELU(BN(h)) @ W1 + b1 ----------------
// CTA 256 thr = 8 warps; tile 128 rows x 64 cols; K=128.
#define LDB 72
__global__ void __launch_bounds__(256, 2) k_gemm2wm(const float* __restrict__ b1,
                                                    const float* __restrict__ gamma,
                                                    const float* __restrict__ beta,
                                                    float* __restrict__ out) {
    extern __shared__ __half sh[];
    __half* hs  = sh;                 // [128][LDX]
    __half* Wsh = sh + 128*LDX;       // [64][LDX]
    __shared__ float sc[128], sf[128];
    __shared__ float biasTile[16*LDB];
    int tid = threadIdx.x;
    int wid = tid >> 5;               // warp_m: 16 rows each
    int row0 = blockIdx.x * 128;

    if (tid < 128) {
        float m = g_sum[tid] * (1.f / Nn);
        float var = g_sq[tid] * (1.f / Nn) - m*m;
        float r = rsqrtf(var + 1e-5f);
        float s = r * gamma[tid];
        sc[tid] = s;
        sf[tid] = beta[tid] - m*s;
    }
    for (int idx = tid; idx < 16*64; idx += 256) {
        int r = idx >> 6, cc = idx & 63;
        biasTile[r*LDB + cc] = b1[cc];
    }
    for (int idx = tid; idx < 1024; idx += 256) {   // W1t: 8192 halves = 1024 uint4
        int n = idx >> 4, ch = idx & 15;
        uint4 v = ((const uint4*)g_W1t)[idx];
        *(uint4*)&Wsh[n*LDX + ch*8] = v;
    }
    __syncthreads();
    for (int idx = tid; idx < 128*128; idx += 256) {
        int r = idx >> 7, k = idx & 127;
        int row = row0 + r;
        float v = 0.f;
        if (row < Nn) {
            v = g_h[row*128 + k] * sc[k] + sf[k];
            v = v > 0.f ? v : expm1f(v);
        }
        hs[r*LDX + k] = __float2half(v);
    }
    __syncthreads();

    wmma::fragment<wmma::accumulator, 16,16,16, float> acc[4];
    #pragma unroll
    for (int j = 0; j < 4; j++)
        wmma::load_matrix_sync(acc[j], biasTile + j*16, LDB, wmma::mem_row_major);

    #pragma unroll
    for (int ks = 0; ks < 8; ks++) {
        wmma::fragment<wmma::matrix_a, 16,16,16, __half, wmma::row_major> af;
        wmma::fragment<wmma::matrix_b, 16,16,16, __half, wmma::col_major> bf[4];
        wmma::load_matrix_sync(af, hs + (wid*16)*LDX + ks*16, LDX);
        #pragma unroll
        for (int j = 0; j < 4; j++)
            wmma::load_matrix_sync(bf[j], Wsh + (j*16)*LDX + ks*16, LDX);
        #pragma unroll
        for (int j = 0; j < 4; j++)
            wmma::mma_sync(acc[j], af, bf[j], acc[j]);
    }

    int r = row0 + wid*16;
    if (r < Nn) {   // 50000 % 16 == 0: tiles are fully in or fully out
        #pragma unroll
        for (int j = 0; j < 4; j++)
            wmma::store_matrix_sync(out + (long)r*64 + j*16, acc[j], 64,
                                    wmma::mem_row_major);
    }
}

// ---------------- launch ----------------
extern "C" void kernel_launch(void* const* d_in, const int* in_sizes, int n_in,
                              void* d_out, int out_size) {
    const void*  A     = d_in[0];
    const float* X     = (const float*)d_in[1];
    const float* Ws    = (const float*)d_in[2];
    const float* W0    = (const float*)d_in[3];
    const float* b0    = (const float*)d_in[4];
    const float* gamma = (const float*)d_in[5];
    const float* beta  = (const float*)d_in[6];
    const float* W1    = (const float*)d_in[7];
    const float* b1    = (const float*)d_in[8];
    float* out = (float*)d_out;

    const int g1_smem = 2 * 128 * LDX * (int)sizeof(__half);         // 69632
    const int g2_smem = (128 + 64) * LDX * (int)sizeof(__half);      // 52224
    cudaFuncSetAttribute(k_gemm1wm, cudaFuncAttributeMaxDynamicSharedMemorySize, g1_smem);
    cudaFuncSetAttribute(k_gemm2wm, cudaFuncAttributeMaxDynamicSharedMemorySize, g2_smem);

    k_dummy<<<1, 32>>>();
    k_prep<<<ZB + FB + W1B + XB, 256>>>(A, X, Ws, W0, W1);
    k_build<<<(TOT + 255)/256, 256>>>(A);
    k_agg<<<(CN*32 + 255)/256, 256>>>();        // ncu slot
    k_gemm1wm<<<NMB, 256, g1_smem>>>(b0);
    k_stats<<<NROWB, 256>>>();
    k_gemm2wm<<<NMB, 256, g2_smem>>>(b1, gamma, beta, out);
}